// round 7
// baseline (speedup 1.0000x reference)
#include <cuda_runtime.h>
#include <cuda_bf16.h>

#define S_GRID 7
#define CH 30
#define TILE 1470          // 7*7*30
#define MAXM 16
#define NUMC 20
#define IPB 16             // images per block
#define THREADS 256
#define MAXPART 2048       // >= B/IPB

__device__ float g_partial[MAXPART];
__device__ unsigned int g_count = 0;

__device__ __forceinline__ float iou_fn(float a0, float a1, float a2, float a3,
                                        float b0, float b1, float b2, float b3) {
    float ax1 = a0 - a2 * 0.5f, ay1 = a1 - a3 * 0.5f;
    float ax2 = a0 + a2 * 0.5f, ay2 = a1 + a3 * 0.5f;
    float bx1 = b0 - b2 * 0.5f, by1 = b1 - b3 * 0.5f;
    float bx2 = b0 + b2 * 0.5f, by2 = b1 + b3 * 0.5f;
    float iw = fmaxf(fminf(ax2, bx2) - fmaxf(ax1, bx1), 0.0f);
    float ih = fmaxf(fminf(ay2, by2) - fmaxf(ay1, by1), 0.0f);
    float inter = iw * ih;
    float uni = a2 * a3 + b2 * b3 - inter;
    return inter / (uni + 1e-6f);
}

__device__ __forceinline__ float block_reduce_256(float v, float* s_red, int t) {
    #pragma unroll
    for (int off = 16; off > 0; off >>= 1)
        v += __shfl_down_sync(0xffffffffu, v, off);
    if ((t & 31) == 0) s_red[t >> 5] = v;
    __syncthreads();
    float r = 0.0f;
    #pragma unroll
    for (int i = 0; i < 8; i++) r += s_red[i];
    return r;
}

__global__ __launch_bounds__(THREADS) void yolo_loss_fused(
    const float* __restrict__ pred,
    const float* __restrict__ gt_xywh,
    const int*   __restrict__ gt_class,
    float* __restrict__ out,
    int nblk, int Btot) {

    const int t = threadIdx.x;
    const long long b0 = (long long)blockIdx.x * IPB;

    __shared__ int s_cell[IPB][MAXM];
    __shared__ unsigned int s_cmask[S_GRID * S_GRID];  // bit im: cell has object in image im
    __shared__ float s_red[8];
    __shared__ int s_last;

    // ---- gt metadata: one box per thread (16 imgs x 16 boxes), coalesced ----
    float4 g = reinterpret_cast<const float4*>(gt_xywh)[(long long)blockIdx.x * THREADS + t];
    int cls  = gt_class[(long long)blockIdx.x * THREADS + t];
    const int img = t >> 4;        // 0..15
    const int m   = t & 15;        // 0..15
    // Faithful to reference: row from x, col from y.
    int row = min(max((int)floorf(g.x * 7.0f), 0), S_GRID - 1);
    int col = min(max((int)floorf(g.y * 7.0f), 0), S_GRID - 1);
    int cell = row * S_GRID + col;
    s_cell[img][m] = cell;
    if (t < S_GRID * S_GRID) s_cmask[t] = 0u;
    __syncthreads();

    atomicOr(&s_cmask[cell], 1u << img);
    // first-occurrence-per-cell dedup
    int keep = 1;
    for (int i = 0; i < m; i++)
        if (s_cell[img][i] == cell) keep = 0;
    __syncthreads();

    float acc = 0.0f;

    // ---- no-object confidence: 16 imgs x 98 slots, threads 0..195 active;
    //      thread owns fixed (cell, ch) slot; 8-deep image loop, +2*TILE step ----
    if (t < 2 * 98) {
        const int i0 = (t >= 98) ? 1 : 0;
        const int r  = t - 98 * i0;
        const int c  = r >> 1;
        const int ch = (r & 1) ? 9 : 4;
        const unsigned int cm = s_cmask[c];
        const float* p = pred + (b0 + i0) * TILE + c * CH + ch;
        float v[8];
        #pragma unroll
        for (int k = 0; k < 8; k++)
            v[k] = __ldg(p + 2 * k * TILE);
        #pragma unroll
        for (int k = 0; k < 8; k++) {
            float w = ((cm >> (i0 + 2 * k)) & 1u) ? 0.0f : 0.5f;  // LAMBDA_NOOBJ
            acc += w * v[k] * v[k];
        }
    }

    // ---- per-box terms: thread t owns (img, m) ----
    if (keep) {
        float tx = g.x * 7.0f - (float)col;      // faithful x/y swap
        float ty = g.y * 7.0f - (float)row;
        float tw = sqrtf(g.z);
        float th = sqrtf(g.w);
        const float2* rp = reinterpret_cast<const float2*>(
            &pred[(b0 + img) * TILE + cell * CH]);   // 8B-aligned row

        float2 v0 = __ldg(&rp[0]);   // ch0,1
        float2 v1 = __ldg(&rp[1]);   // ch2,3
        float2 v2 = __ldg(&rp[2]);   // ch4,5
        float2 v3 = __ldg(&rp[3]);   // ch6,7
        float2 v4 = __ldg(&rp[4]);   // ch8,9

        float i1 = iou_fn(v0.x, v0.y, v1.x, v1.y, tx, ty, tw, th);
        float i2 = iou_fn(v2.y, v3.x, v3.y, v4.x, tx, ty, tw, th);
        bool use2 = (i2 >= i1);
        float bx = use2 ? v2.y : v0.x;
        float by = use2 ? v3.x : v0.y;
        float bw = use2 ? v3.y : v1.x;
        float bh = use2 ? v4.x : v1.y;
        float sc = use2 ? v4.y : v2.x;
        float si = use2 ? i2   : i1;

        float d0 = bx - tx, d1 = by - ty, d2 = bw - tw, d3 = bh - th;
        acc += 5.0f * (d0 * d0 + d1 * d1 + d2 * d2 + d3 * d3);  // LAMBDA_COORD
        float dc = sc - si;
        acc += dc * dc;

        // classes: channels 10..29, streamed as float2
        #pragma unroll
        for (int i = 0; i < 10; i++) {
            float2 v = __ldg(&rp[5 + i]);
            float e0 = v.x - ((2 * i     == cls) ? 1.0f : 0.0f);
            float e1 = v.y - ((2 * i + 1 == cls) ? 1.0f : 0.0f);
            acc += e0 * e0 + e1 * e1;
        }
    }

    // ---- block partial ----
    float tot = block_reduce_256(acc, s_red, t);
    if (t == 0) g_partial[blockIdx.x] = tot;

    // ---- fused final reduction: last block finishes ----
    __threadfence();
    if (t == 0) {
        unsigned int ticket = atomicAdd(&g_count, 1u);
        s_last = (ticket == (unsigned int)(nblk - 1));
    }
    __syncthreads();
    if (s_last) {
        __threadfence();
        float s = 0.0f;
        for (int i = t; i < nblk; i += THREADS)
            s += __ldcg(&g_partial[i]);
        __syncthreads();          // s_red reuse
        float fin = block_reduce_256(s, s_red, t);
        if (t == 0) {
            out[0] = fin / (float)Btot;
            g_count = 0;          // ready for next (replay) launch
        }
    }
}

extern "C" void kernel_launch(void* const* d_in, const int* in_sizes, int n_in,
                              void* d_out, int out_size) {
    const float* pred    = (const float*)d_in[0];
    const float* gt_xywh = (const float*)d_in[1];
    const int*   gt_cls  = (const int*)d_in[2];
    float* out = (float*)d_out;

    int B = in_sizes[0] / TILE;     // 16384
    int nblk = B / IPB;             // 1024

    yolo_loss_fused<<<nblk, THREADS>>>(pred, gt_xywh, gt_cls, out, nblk, B);
}